// round 4
// baseline (speedup 1.0000x reference)
#include <cuda_runtime.h>
#include <cuda_bf16.h>
#include <cstdint>

#define BB 4
#define NN 20000
#define HH 448
#define WW 448
#define HWSZ (HH*WW)          // 200704
#define PTS (2*BB*NN)         // 160000 point-instances per role

// ---------------- device scratch (static globals; no runtime alloc) -------------
__device__ __align__(16) float g_q[(size_t)PTS*32];
__device__ __align__(16) float g_k[(size_t)PTS*32];
__device__ __align__(16) float g_v[(size_t)PTS*32];
__device__ float g_sinv[(size_t)PTS*2];
__device__ __align__(16) int   g_lut[2*BB*HWSZ];

__device__ float g_W[2][4][32][32];   // [dir][m][in_ch][out_ch]; m: 0=q 1=k 2=v 3=out
__device__ float g_bq[2][32], g_bkv[2][32], g_bkinv[2][32];
__device__ float g_bv0[2][32], g_bvinv[2][32], g_bo[2][32];
__device__ float g_pv[2][9][32];

__constant__ int c_sh[9][2] = {{0,0},{-1,0},{1,0},{0,1},{-1,1},{1,1},{0,-1},{-1,-1},{1,-1}};

// ---------------- K1: fold weight chains into effective matrices ----------------
__global__ void k_prep(const float* qw1, const float* qb1,
                       const float* qw2, const float* qb2,
                       const float* posw, const float* posb,
                       const float* iw1, const float* ib1, const float* ow1, const float* ob1,
                       const float* iw2, const float* ib2, const float* ow2, const float* ob2)
{
    int d = blockIdx.x;          // direction
    int m = blockIdx.y;          // 0..3
    int t = threadIdx.x;         // 0..1023
    const float* qkvw = d ? qw2 : qw1;
    const float* qkvb = d ? qb2 : qb1;
    const float* iw   = d ? iw2 : iw1;
    const float* ib   = d ? ib2 : ib1;
    const float* ow   = d ? ow2 : ow1;
    const float* ob   = d ? ob2 : ob1;

    if (m < 3) {
        // Weff[i][j] = sum_c in_w[m*32+i][c] * qkv_w[m][c][j]; store transposed [j][i]
        int i = t >> 5, j = t & 31;
        float acc = 0.f;
        #pragma unroll
        for (int c = 0; c < 32; c++)
            acc = fmaf(iw[(m*32+i)*32 + c], qkvw[(m*32+c)*32 + j], acc);
        g_W[d][m][j][i] = acc;
    } else {
        // Wo transpose-copy
        int i = t >> 5, j = t & 31;
        g_W[d][3][j][i] = ow[i*32 + j];
        if (t < 32) {
            int i2 = t;
            float aq = ib[i2], ak = ib[32+i2], av = ib[64+i2];
            #pragma unroll
            for (int c = 0; c < 32; c++) {
                aq = fmaf(iw[i2*32 + c],        qkvb[c],      aq);
                ak = fmaf(iw[(32+i2)*32 + c],   qkvb[32+c],   ak);
                av = fmaf(iw[(64+i2)*32 + c],   qkvb[64+c],   av);
            }
            g_bq[d][i2]    = aq;
            g_bkv[d][i2]   = ak;
            g_bkinv[d][i2] = ib[32+i2];
            g_bv0[d][i2]   = av;
            g_bvinv[d][i2] = ib[64+i2];
            g_bo[d][i2]    = ob[i2];
        } else if (t < 32 + 9*32) {
            int s = (t - 32) >> 5, i2 = t & 31;
            float acc = 0.f;
            #pragma unroll
            for (int c = 0; c < 32; c++) {
                float pc = (float)c_sh[s][0]*posw[2*c] + (float)c_sh[s][1]*posw[2*c+1] + posb[c];
                acc = fmaf(iw[(64+i2)*32 + c], pc, acc);
            }
            g_pv[d][s][i2] = acc;
        }
    }
}

// ---------------- K2: zero output canvas + LUT = -1 -----------------------------
__global__ void k_zero(float4* out4, int n_out4)
{
    int i = blockIdx.x * blockDim.x + threadIdx.x;
    if (i < n_out4) {
        out4[i] = make_float4(0.f, 0.f, 0.f, 0.f);
    } else {
        int j = i - n_out4;
        if (j < (2*BB*HWSZ)/4) {
            ((int4*)g_lut)[j] = make_int4(-1, -1, -1, -1);
        }
    }
}

// ---------------- K3: layernorm + fused projections + LUT scatter ----------------
__global__ void k_pre(const float* li_f, const float* ra_f,
                      const int* li_c, const int* ra_c,
                      const float* li_nw, const float* li_nb,
                      const float* ra_nw, const float* ra_nb)
{
    __shared__ float sb[8][32];
    int lane = threadIdx.x & 31, wid = threadIdx.x >> 5;
    int wg = blockIdx.x * 8 + wid;
    if (wg >= PTS) return;
    int set = wg / (BB*NN);
    int rem = wg - set * (BB*NN);
    int b = rem / NN, j = rem - b * NN;

    const float* feat = (set ? ra_f : li_f) + (size_t)(b*NN + j) * 32;
    float x = feat[lane];
    float s = x;
    #pragma unroll
    for (int o = 16; o; o >>= 1) s += __shfl_xor_sync(~0u, s, o);
    float mu = s * (1.f/32.f);
    float dx = x - mu;
    float vv = dx * dx;
    #pragma unroll
    for (int o = 16; o; o >>= 1) vv += __shfl_xor_sync(~0u, vv, o);
    float nf = dx * rsqrtf(vv * (1.f/32.f) + 1e-5f);
    nf = nf * (set ? ra_nw : li_nw)[lane] + (set ? ra_nb : li_nb)[lane];

    sb[wid][lane] = nf;
    __syncwarp();

    int dq = set, dk = set ^ 1;
    float aq = g_bq[dq][lane], ak = g_bkv[dk][lane], av = g_bv0[dk][lane];
    #pragma unroll
    for (int c = 0; c < 32; c++) {
        float f = sb[wid][c];
        aq = fmaf(f, g_W[dq][0][c][lane], aq);
        ak = fmaf(f, g_W[dk][1][c][lane], ak);
        av = fmaf(f, g_W[dk][2][c][lane], av);
    }
    size_t pq = ((size_t)(dq*BB + b) * NN + j);
    size_t pk = ((size_t)(dk*BB + b) * NN + j);
    g_q[pq*32 + lane] = aq;
    g_k[pk*32 + lane] = ak;
    g_v[pk*32 + lane] = av;

    // precompute invalid-neighbor score: dot(q, bk_inv)/4 per head
    float p = aq * g_bkinv[dq][lane];
    p += __shfl_xor_sync(~0u, p, 8);
    p += __shfl_xor_sync(~0u, p, 4);
    p += __shfl_xor_sync(~0u, p, 2);
    p += __shfl_xor_sync(~0u, p, 1);
    if ((lane & 15) == 0) g_sinv[pq*2 + (lane >> 4)] = p * 0.25f;

    if (lane == 0) {
        const int* cc = (set ? ra_c : li_c) + (size_t)(b*NN + j) * 2;
        g_lut[(dk*BB + b) * HWSZ + cc[0]*WW + cc[1]] = j;
    }
}

// ---------------- K4: sparse 9-neighbor attention + out-proj + scatter -----------
__global__ void k_attn(const int* li_c, const int* ra_c, float* __restrict__ out)
{
    __shared__ float sb[8][32];
    int lane = threadIdx.x & 31, wid = threadIdx.x >> 5;
    int wg = blockIdx.x * 8 + wid;
    if (wg >= PTS) return;
    int d = wg / (BB*NN);
    int rem = wg - d * (BB*NN);
    int b = rem / NN, j = rem - b * NN;

    const int* cc = (d == 0 ? li_c : ra_c) + (size_t)(b*NN + j) * 2;
    int h = cc[0], w = cc[1];

    size_t pbase = ((size_t)(d*BB + b) * NN + j);
    float qv = g_q[pbase*32 + lane];
    int head = lane >> 4;
    float sinv = g_sinv[pbase*2 + head];
    const int* lut = g_lut + (d*BB + b) * HWSZ;
    size_t kvbase = (size_t)(d*BB + b) * NN;

    float sc[9], vreg[9];
    unsigned vm = 0;
    #pragma unroll
    for (int s = 0; s < 9; s++) {
        int sh = h + c_sh[s][0], sw = w + c_sh[s][1];
        int idx = -1;
        if ((unsigned)sh < (unsigned)HH && (unsigned)sw < (unsigned)WW)
            idx = lut[sh*WW + sw];
        if (idx >= 0) {   // warp-uniform branch
            size_t off = (kvbase + idx) * 32 + lane;
            float kc = g_k[off];
            float p = qv * kc;
            p += __shfl_xor_sync(~0u, p, 8);
            p += __shfl_xor_sync(~0u, p, 4);
            p += __shfl_xor_sync(~0u, p, 2);
            p += __shfl_xor_sync(~0u, p, 1);
            sc[s] = p * 0.25f;
            vreg[s] = g_v[off] + g_pv[d][s][lane];
            vm |= (1u << s);
        } else {
            sc[s] = sinv;
            vreg[s] = 0.f;
        }
    }
    float mx = sc[0];
    #pragma unroll
    for (int s = 1; s < 9; s++) mx = fmaxf(mx, sc[s]);
    float sum = 0.f;
    #pragma unroll
    for (int s = 0; s < 9; s++) { sc[s] = __expf(sc[s] - mx); sum += sc[s]; }
    float inv = 1.f / sum;
    float o = 0.f, winv = 0.f;
    #pragma unroll
    for (int s = 0; s < 9; s++) {
        float ws = sc[s] * inv;
        if (vm & (1u << s)) o = fmaf(ws, vreg[s], o);
        else                winv += ws;
    }
    o = fmaf(winv, g_bvinv[d][lane], o);

    sb[wid][lane] = o;
    __syncwarp();
    float acc = g_bo[d][lane];
    #pragma unroll
    for (int c = 0; c < 32; c++)
        acc = fmaf(sb[wid][c], g_W[d][3][c][lane], acc);

    out[((size_t)(d*BB + b) * 32 + lane) * HWSZ + h*WW + w] = acc;
}

// --------------------------------- launch ---------------------------------------
extern "C" void kernel_launch(void* const* d_in, const int* in_sizes, int n_in,
                              void* d_out, int out_size)
{
    const float* li_f  = (const float*)d_in[0];
    const float* ra_f  = (const float*)d_in[1];
    const int*   li_c  = (const int*)d_in[2];
    const int*   ra_c  = (const int*)d_in[3];
    const float* li_nw = (const float*)d_in[4];
    const float* li_nb = (const float*)d_in[5];
    const float* ra_nw = (const float*)d_in[6];
    const float* ra_nb = (const float*)d_in[7];
    const float* qw1   = (const float*)d_in[8];
    const float* qb1   = (const float*)d_in[9];
    const float* qw2   = (const float*)d_in[10];
    const float* qb2   = (const float*)d_in[11];
    const float* posw  = (const float*)d_in[12];
    const float* posb  = (const float*)d_in[13];
    const float* iw1   = (const float*)d_in[14];
    const float* ib1   = (const float*)d_in[15];
    const float* ow1   = (const float*)d_in[16];
    const float* ob1   = (const float*)d_in[17];
    const float* iw2   = (const float*)d_in[18];
    const float* ib2   = (const float*)d_in[19];
    const float* ow2   = (const float*)d_in[20];
    const float* ob2   = (const float*)d_in[21];

    k_prep<<<dim3(2,4), 1024>>>(qw1, qb1, qw2, qb2, posw, posb,
                                iw1, ib1, ow1, ob1, iw2, ib2, ow2, ob2);

    int n_out4 = out_size / 4;
    int n_tot  = n_out4 + (2*BB*HWSZ)/4;
    k_zero<<<(n_tot + 255)/256, 256>>>((float4*)d_out, n_out4);

    k_pre<<<(PTS + 7)/8, 256>>>(li_f, ra_f, li_c, ra_c, li_nw, li_nb, ra_nw, ra_nb);

    k_attn<<<(PTS + 7)/8, 256>>>(li_c, ra_c, (float*)d_out);
}

// round 7
// speedup vs baseline: 1.2179x; 1.2179x over previous
#include <cuda_runtime.h>
#include <cuda_bf16.h>
#include <cstdint>

#define BB 4
#define NN 20000
#define HH 448
#define WW 448
#define HWSZ (HH*WW)          // 200704
#define PTS (2*BB*NN)         // 160000 point-instances per role

// ---------------- device scratch (static globals; no runtime alloc) -------------
__device__ __align__(16) float g_q[(size_t)PTS*32];
__device__ __align__(16) float g_k[(size_t)PTS*32];
__device__ __align__(16) float g_v[(size_t)PTS*32];
__device__ __align__(16) float g_o[(size_t)PTS*32];   // compact attention output
__device__ float g_sinv[(size_t)PTS*2];
__device__ __align__(16) int   g_lut[2*BB*HWSZ];

__device__ float g_W[2][4][32][32];   // [dir][m][in_ch][out_ch]; m: 0=q 1=k 2=v 3=out
__device__ float g_bq[2][32], g_bkv[2][32], g_bkinv[2][32];
__device__ float g_bv0[2][32], g_bvinv[2][32], g_bo[2][32];
__device__ float g_pv[2][9][32];

__constant__ int c_sh[9][2] = {{0,0},{-1,0},{1,0},{0,1},{-1,1},{1,1},{0,-1},{-1,-1},{1,-1}};

// ---------------- K1: fold weight chains into effective matrices ----------------
__global__ void k_prep(const float* qw1, const float* qb1,
                       const float* qw2, const float* qb2,
                       const float* posw, const float* posb,
                       const float* iw1, const float* ib1, const float* ow1, const float* ob1,
                       const float* iw2, const float* ib2, const float* ow2, const float* ob2)
{
    int d = blockIdx.x;          // direction
    int m = blockIdx.y;          // 0..3
    int t = threadIdx.x;         // 0..1023
    const float* qkvw = d ? qw2 : qw1;
    const float* qkvb = d ? qb2 : qb1;
    const float* iw   = d ? iw2 : iw1;
    const float* ib   = d ? ib2 : ib1;
    const float* ow   = d ? ow2 : ow1;
    const float* ob   = d ? ob2 : ob1;

    if (m < 3) {
        // Weff[i][j] = sum_c in_w[m*32+i][c] * qkv_w[m][c][j]; store transposed [j][i]
        int i = t >> 5, j = t & 31;
        float acc = 0.f;
        #pragma unroll
        for (int c = 0; c < 32; c++)
            acc = fmaf(iw[(m*32+i)*32 + c], qkvw[(m*32+c)*32 + j], acc);
        g_W[d][m][j][i] = acc;
    } else {
        int i = t >> 5, j = t & 31;
        g_W[d][3][j][i] = ow[i*32 + j];
        if (t < 32) {
            int i2 = t;
            float aq = ib[i2], ak = ib[32+i2], av = ib[64+i2];
            #pragma unroll
            for (int c = 0; c < 32; c++) {
                aq = fmaf(iw[i2*32 + c],        qkvb[c],      aq);
                ak = fmaf(iw[(32+i2)*32 + c],   qkvb[32+c],   ak);
                av = fmaf(iw[(64+i2)*32 + c],   qkvb[64+c],   av);
            }
            g_bq[d][i2]    = aq;
            g_bkv[d][i2]   = ak;
            g_bkinv[d][i2] = ib[32+i2];
            g_bv0[d][i2]   = av;
            g_bvinv[d][i2] = ib[64+i2];
            g_bo[d][i2]    = ob[i2];
        } else if (t < 32 + 9*32) {
            int s = (t - 32) >> 5, i2 = t & 31;
            float acc = 0.f;
            #pragma unroll
            for (int c = 0; c < 32; c++) {
                float pc = (float)c_sh[s][0]*posw[2*c] + (float)c_sh[s][1]*posw[2*c+1] + posb[c];
                acc = fmaf(iw[(64+i2)*32 + c], pc, acc);
            }
            g_pv[d][s][i2] = acc;
        }
    }
}

// ---------------- K2: LUT = -1 ---------------------------------------------------
__global__ void k_lutclr()
{
    int i = blockIdx.x * blockDim.x + threadIdx.x;
    if (i < (2*BB*HWSZ)/4)
        ((int4*)g_lut)[i] = make_int4(-1, -1, -1, -1);
}

// ---------------- K3: layernorm + fused projections + LUT scatter ----------------
__global__ void k_pre(const float* __restrict__ li_f, const float* __restrict__ ra_f,
                      const int* __restrict__ li_c, const int* __restrict__ ra_c,
                      const float* __restrict__ li_nw, const float* __restrict__ li_nb,
                      const float* __restrict__ ra_nw, const float* __restrict__ ra_nb)
{
    __shared__ float sb[8][32];
    int lane = threadIdx.x & 31, wid = threadIdx.x >> 5;
    int wg = blockIdx.x * 8 + wid;
    if (wg >= PTS) return;
    int set = wg / (BB*NN);
    int rem = wg - set * (BB*NN);
    int b = rem / NN, j = rem - b * NN;

    const float* feat = (set ? ra_f : li_f) + (size_t)(b*NN + j) * 32;
    float x = feat[lane];
    float s = x;
    #pragma unroll
    for (int o = 16; o; o >>= 1) s += __shfl_xor_sync(~0u, s, o);
    float mu = s * (1.f/32.f);
    float dx = x - mu;
    float vv = dx * dx;
    #pragma unroll
    for (int o = 16; o; o >>= 1) vv += __shfl_xor_sync(~0u, vv, o);
    float nf = dx * rsqrtf(vv * (1.f/32.f) + 1e-5f);
    nf = nf * (set ? ra_nw : li_nw)[lane] + (set ? ra_nb : li_nb)[lane];

    sb[wid][lane] = nf;
    __syncwarp();

    int dq = set, dk = set ^ 1;
    float aq = g_bq[dq][lane], ak = g_bkv[dk][lane], av = g_bv0[dk][lane];
    #pragma unroll
    for (int c = 0; c < 32; c++) {
        float f = sb[wid][c];
        aq = fmaf(f, g_W[dq][0][c][lane], aq);
        ak = fmaf(f, g_W[dk][1][c][lane], ak);
        av = fmaf(f, g_W[dk][2][c][lane], av);
    }
    size_t pq = ((size_t)(dq*BB + b) * NN + j);
    size_t pk = ((size_t)(dk*BB + b) * NN + j);
    g_q[pq*32 + lane] = aq;
    g_k[pk*32 + lane] = ak;
    g_v[pk*32 + lane] = av;

    // precompute invalid-neighbor score: dot(q, bk_inv)/4 per head
    float p = aq * g_bkinv[dq][lane];
    p += __shfl_xor_sync(~0u, p, 8);
    p += __shfl_xor_sync(~0u, p, 4);
    p += __shfl_xor_sync(~0u, p, 2);
    p += __shfl_xor_sync(~0u, p, 1);
    if ((lane & 15) == 0) g_sinv[pq*2 + (lane >> 4)] = p * 0.25f;

    if (lane == 0) {
        const int* cc = (set ? ra_c : li_c) + (size_t)(b*NN + j) * 2;
        g_lut[(dk*BB + b) * HWSZ + cc[0]*WW + cc[1]] = j;
    }
}

// ---------------- K4: sparse 9-neighbor attention + out-proj (compact write) -----
__global__ void k_attn(const int* __restrict__ li_c, const int* __restrict__ ra_c)
{
    __shared__ float sb[8][32];
    int lane = threadIdx.x & 31, wid = threadIdx.x >> 5;
    int wg = blockIdx.x * 8 + wid;
    if (wg >= PTS) return;
    int d = wg / (BB*NN);
    int rem = wg - d * (BB*NN);
    int b = rem / NN, j = rem - b * NN;

    const int* cc = (d == 0 ? li_c : ra_c) + (size_t)(b*NN + j) * 2;
    int h = cc[0], w = cc[1];

    size_t pbase = ((size_t)(d*BB + b) * NN + j);
    float qv = g_q[pbase*32 + lane];
    int head = lane >> 4;
    float sinv = g_sinv[pbase*2 + head];
    const int* lut = g_lut + (d*BB + b) * HWSZ;
    size_t kvbase = (size_t)(d*BB + b) * NN;

    float sc[9], vreg[9];
    unsigned vm = 0;
    #pragma unroll
    for (int s = 0; s < 9; s++) {
        int sh = h + c_sh[s][0], sw = w + c_sh[s][1];
        int idx = -1;
        if ((unsigned)sh < (unsigned)HH && (unsigned)sw < (unsigned)WW)
            idx = __ldg(&lut[sh*WW + sw]);
        if (idx >= 0) {   // warp-uniform branch
            size_t off = (kvbase + idx) * 32 + lane;
            float kc = g_k[off];
            float p = qv * kc;
            p += __shfl_xor_sync(~0u, p, 8);
            p += __shfl_xor_sync(~0u, p, 4);
            p += __shfl_xor_sync(~0u, p, 2);
            p += __shfl_xor_sync(~0u, p, 1);
            sc[s] = p * 0.25f;
            vreg[s] = g_v[off] + g_pv[d][s][lane];
            vm |= (1u << s);
        } else {
            sc[s] = sinv;
            vreg[s] = 0.f;
        }
    }
    float mx = sc[0];
    #pragma unroll
    for (int s = 1; s < 9; s++) mx = fmaxf(mx, sc[s]);
    float sum = 0.f;
    #pragma unroll
    for (int s = 0; s < 9; s++) { sc[s] = __expf(sc[s] - mx); sum += sc[s]; }
    float inv = 1.f / sum;
    float o = 0.f, winv = 0.f;
    #pragma unroll
    for (int s = 0; s < 9; s++) {
        float ws = sc[s] * inv;
        if (vm & (1u << s)) o = fmaf(ws, vreg[s], o);
        else                winv += ws;
    }
    o = fmaf(winv, g_bvinv[d][lane], o);

    sb[wid][lane] = o;
    __syncwarp();
    float acc = g_bo[d][lane];
    #pragma unroll
    for (int c = 0; c < 32; c++)
        acc = fmaf(sb[wid][c], g_W[d][3][c][lane], acc);

    g_o[pbase*32 + lane] = acc;        // compact, fully coalesced
}

// ---------------- K5: fused canvas zero + scatter (canvas-major, coalesced) ------
// blockIdx.y = db in [0,8): d = db>>2, b = db&3. One thread per pixel, 8 float4
// channel-iterations; every store is a coalesced 128B line per warp.
__global__ void k_scatter(float* __restrict__ out)
{
    int pix = blockIdx.x * blockDim.x + threadIdx.x;
    if (pix >= HWSZ) return;
    int db = blockIdx.y;
    int d = db >> 2, b = db & 3;

    // query coords of direction d live in lut slot ((d^1)*BB + b)
    int idx = __ldg(&g_lut[((d ^ 1)*BB + b) * HWSZ + pix]);
    const float4* src = (const float4*)(g_o + ((size_t)(d*BB + b) * NN + (idx < 0 ? 0 : idx)) * 32);
    float* dst = out + ((size_t)db * 32) * HWSZ + pix;

    #pragma unroll
    for (int c4 = 0; c4 < 8; c4++) {
        float4 v = make_float4(0.f, 0.f, 0.f, 0.f);
        if (idx >= 0) v = __ldg(&src[c4]);
        dst[(c4*4 + 0) * HWSZ] = v.x;
        dst[(c4*4 + 1) * HWSZ] = v.y;
        dst[(c4*4 + 2) * HWSZ] = v.z;
        dst[(c4*4 + 3) * HWSZ] = v.w;
    }
}

// --------------------------------- launch ---------------------------------------
extern "C" void kernel_launch(void* const* d_in, const int* in_sizes, int n_in,
                              void* d_out, int out_size)
{
    const float* li_f  = (const float*)d_in[0];
    const float* ra_f  = (const float*)d_in[1];
    const int*   li_c  = (const int*)d_in[2];
    const int*   ra_c  = (const int*)d_in[3];
    const float* li_nw = (const float*)d_in[4];
    const float* li_nb = (const float*)d_in[5];
    const float* ra_nw = (const float*)d_in[6];
    const float* ra_nb = (const float*)d_in[7];
    const float* qw1   = (const float*)d_in[8];
    const float* qb1   = (const float*)d_in[9];
    const float* qw2   = (const float*)d_in[10];
    const float* qb2   = (const float*)d_in[11];
    const float* posw  = (const float*)d_in[12];
    const float* posb  = (const float*)d_in[13];
    const float* iw1   = (const float*)d_in[14];
    const float* ib1   = (const float*)d_in[15];
    const float* ow1   = (const float*)d_in[16];
    const float* ob1   = (const float*)d_in[17];
    const float* iw2   = (const float*)d_in[18];
    const float* ib2   = (const float*)d_in[19];
    const float* ow2   = (const float*)d_in[20];
    const float* ob2   = (const float*)d_in[21];

    k_prep<<<dim3(2,4), 1024>>>(qw1, qb1, qw2, qb2, posw, posb,
                                iw1, ib1, ow1, ob1, iw2, ib2, ow2, ob2);

    k_lutclr<<<((2*BB*HWSZ)/4 + 255)/256, 256>>>();

    k_pre<<<(PTS + 7)/8, 256>>>(li_f, ra_f, li_c, ra_c, li_nw, li_nb, ra_nw, ra_nb);

    k_attn<<<(PTS + 7)/8, 256>>>(li_c, ra_c);

    k_scatter<<<dim3((HWSZ + 255)/256, 2*BB), 256>>>((float*)d_out);
}